// round 1
// baseline (speedup 1.0000x reference)
#include <cuda_runtime.h>

#define BN_EPS 1e-5f

#define MAXN 100000
#define MAXE 400000
#define MAXT 1000000

// ---- scratch (allocation-free, static device globals) ----
__device__ float g_Vsrc[(size_t)MAXN * 256];   // [N,256] = [core_src | gate_src]
__device__ float g_Vdst[(size_t)MAXN * 256];   // [N,256] = [core_dst | gate_dst]
__device__ float g_Ep  [(size_t)MAXE * 256];   // [E,256] = [core_bond | gate_bond]
__device__ float g_A   [(size_t)MAXT * 256];   // [T,256] = angle proj, overwritten in-place with core|gate
__device__ float g_seg [(size_t)MAXE * 128];   // segment sums
__device__ float g_stats[512];                 // sumC | ssqC | sumG | ssqG
__device__ float g_scale[512];                 // aC | bC | aG | bG

// ------------------------------------------------------------------
// zero segment buffer + stats (must happen every launch: graph replays)
// ------------------------------------------------------------------
__global__ void zero_kernel(int E) {
    size_t n4 = (size_t)E * 32;  // E*128 floats / 4
    size_t i = (size_t)blockIdx.x * blockDim.x + threadIdx.x;
    size_t st = (size_t)gridDim.x * blockDim.x;
    float4 z = make_float4(0.f, 0.f, 0.f, 0.f);
    float4* p = reinterpret_cast<float4*>(g_seg);
    for (size_t k = i; k < n4; k += st) p[k] = z;
    if (i < 512) g_stats[i] = 0.f;
}

// ------------------------------------------------------------------
// SGEMM: C[m, coff + n] = sum_k X[m,k] * W[n,k]  (+ optional Dadd)
// X: [M,K] row-major, W: [128,K] row-major, C row stride = ldc.
// BM=BN=128, BK=16, 256 threads, 8x8 per thread.
// ------------------------------------------------------------------
__global__ __launch_bounds__(256)
void sgemm_xwT(const float* __restrict__ X, const float* __restrict__ W,
               const float* __restrict__ Dadd, float* __restrict__ C,
               int M, int K, int ldc, int coff) {
    __shared__ float Xs[16][132];
    __shared__ float Ws[16][132];

    const int tid = threadIdx.x;
    const int row0 = blockIdx.x * 128;
    const int tx = tid & 15;
    const int ty = tid >> 4;

    float acc[8][8];
#pragma unroll
    for (int i = 0; i < 8; ++i)
#pragma unroll
        for (int j = 0; j < 8; ++j) acc[i][j] = 0.f;

    const int lrow = tid >> 2;        // 0..63
    const int lk4  = (tid & 3) * 4;   // 0,4,8,12

    for (int k0 = 0; k0 < K; k0 += 16) {
        // load X tile (transposed into Xs[k][m]), predicated on M
#pragma unroll
        for (int l = 0; l < 2; ++l) {
            int m = l * 64 + lrow;
            int gr = row0 + m;
            float4 v = make_float4(0.f, 0.f, 0.f, 0.f);
            if (gr < M)
                v = *reinterpret_cast<const float4*>(X + (size_t)gr * K + k0 + lk4);
            Xs[lk4 + 0][m] = v.x;
            Xs[lk4 + 1][m] = v.y;
            Xs[lk4 + 2][m] = v.z;
            Xs[lk4 + 3][m] = v.w;
        }
        // load W tile (transposed into Ws[k][n]); W always has 128 rows
#pragma unroll
        for (int l = 0; l < 2; ++l) {
            int n = l * 64 + lrow;
            float4 v = *reinterpret_cast<const float4*>(W + (size_t)n * K + k0 + lk4);
            Ws[lk4 + 0][n] = v.x;
            Ws[lk4 + 1][n] = v.y;
            Ws[lk4 + 2][n] = v.z;
            Ws[lk4 + 3][n] = v.w;
        }
        __syncthreads();

#pragma unroll
        for (int kk = 0; kk < 16; ++kk) {
            float4 x0 = *reinterpret_cast<const float4*>(&Xs[kk][ty * 8]);
            float4 x1 = *reinterpret_cast<const float4*>(&Xs[kk][ty * 8 + 4]);
            float4 w0 = *reinterpret_cast<const float4*>(&Ws[kk][tx * 8]);
            float4 w1 = *reinterpret_cast<const float4*>(&Ws[kk][tx * 8 + 4]);
            float xr[8] = {x0.x, x0.y, x0.z, x0.w, x1.x, x1.y, x1.z, x1.w};
            float wr[8] = {w0.x, w0.y, w0.z, w0.w, w1.x, w1.y, w1.z, w1.w};
#pragma unroll
            for (int i = 0; i < 8; ++i)
#pragma unroll
                for (int j = 0; j < 8; ++j)
                    acc[i][j] = fmaf(xr[i], wr[j], acc[i][j]);
        }
        __syncthreads();
    }

    // epilogue
#pragma unroll
    for (int i = 0; i < 8; ++i) {
        int gr = row0 + ty * 8 + i;
        if (gr >= M) continue;
        float* crow = C + (size_t)gr * ldc + coff + tx * 8;
        float4 o0 = make_float4(acc[i][0], acc[i][1], acc[i][2], acc[i][3]);
        float4 o1 = make_float4(acc[i][4], acc[i][5], acc[i][6], acc[i][7]);
        if (Dadd) {
            const float* drow = Dadd + (size_t)gr * ldc + coff + tx * 8;
            float4 d0 = *reinterpret_cast<const float4*>(drow);
            float4 d1 = *reinterpret_cast<const float4*>(drow + 4);
            o0.x += d0.x; o0.y += d0.y; o0.z += d0.z; o0.w += d0.w;
            o1.x += d1.x; o1.y += d1.y; o1.z += d1.z; o1.w += d1.w;
        }
        *reinterpret_cast<float4*>(crow)     = o0;
        *reinterpret_cast<float4*>(crow + 4) = o1;
    }
}

// ------------------------------------------------------------------
// pass B: per triplet, core/gate = A + Vsrc[j] + Ep[k] + Vdst[i];
// written in-place over g_A; accumulate per-column sum/sumsq.
// one warp per triplet, lane covers 4 columns (lane*4 .. +3).
// ------------------------------------------------------------------
__device__ __forceinline__ float4 f4add(float4 a, float4 b) {
    return make_float4(a.x + b.x, a.y + b.y, a.z + b.z, a.w + b.w);
}

__global__ void pass_fuse(const int* __restrict__ kx, const int* __restrict__ jx,
                          const int* __restrict__ ix, int T) {
    const int lane = threadIdx.x & 31;
    int warp = (blockIdx.x * blockDim.x + threadIdx.x) >> 5;
    const int nw = (gridDim.x * blockDim.x) >> 5;

    float4 sc = make_float4(0, 0, 0, 0), qc = make_float4(0, 0, 0, 0);
    float4 sg = make_float4(0, 0, 0, 0), qg = make_float4(0, 0, 0, 0);

    for (int t = warp; t < T; t += nw) {
        int j = jx[t], k = kx[t], i = ix[t];
        float4* A        = reinterpret_cast<float4*>(g_A + (size_t)t * 256);
        const float4* Vs = reinterpret_cast<const float4*>(g_Vsrc + (size_t)j * 256);
        const float4* Ep = reinterpret_cast<const float4*>(g_Ep + (size_t)k * 256);
        const float4* Vd = reinterpret_cast<const float4*>(g_Vdst + (size_t)i * 256);

        float4 c = f4add(f4add(A[lane], Vs[lane]), f4add(Ep[lane], Vd[lane]));
        float4 g = f4add(f4add(A[lane + 32], Vs[lane + 32]),
                         f4add(Ep[lane + 32], Vd[lane + 32]));
        A[lane] = c;
        A[lane + 32] = g;

        sc = f4add(sc, c);
        qc = f4add(qc, make_float4(c.x * c.x, c.y * c.y, c.z * c.z, c.w * c.w));
        sg = f4add(sg, g);
        qg = f4add(qg, make_float4(g.x * g.x, g.y * g.y, g.z * g.z, g.w * g.w));
    }

    int c0 = lane * 4;
    atomicAdd(&g_stats[c0 + 0], sc.x); atomicAdd(&g_stats[c0 + 1], sc.y);
    atomicAdd(&g_stats[c0 + 2], sc.z); atomicAdd(&g_stats[c0 + 3], sc.w);
    atomicAdd(&g_stats[128 + c0 + 0], qc.x); atomicAdd(&g_stats[128 + c0 + 1], qc.y);
    atomicAdd(&g_stats[128 + c0 + 2], qc.z); atomicAdd(&g_stats[128 + c0 + 3], qc.w);
    atomicAdd(&g_stats[256 + c0 + 0], sg.x); atomicAdd(&g_stats[256 + c0 + 1], sg.y);
    atomicAdd(&g_stats[256 + c0 + 2], sg.z); atomicAdd(&g_stats[256 + c0 + 3], sg.w);
    atomicAdd(&g_stats[384 + c0 + 0], qg.x); atomicAdd(&g_stats[384 + c0 + 1], qg.y);
    atomicAdd(&g_stats[384 + c0 + 2], qg.z); atomicAdd(&g_stats[384 + c0 + 3], qg.w);
}

// ------------------------------------------------------------------
// fold BN into per-column affine: x_norm = x*a + b
// ------------------------------------------------------------------
__global__ void finalize_stats(const float* __restrict__ gamC, const float* __restrict__ betC,
                               const float* __restrict__ gamG, const float* __restrict__ betG,
                               float invT) {
    int c = threadIdx.x;  // 128 threads
    float m = g_stats[c] * invT;
    float v = g_stats[128 + c] * invT - m * m;
    float a = rsqrtf(v + BN_EPS) * gamC[c];
    g_scale[c] = a;
    g_scale[128 + c] = betC[c] - m * a;

    m = g_stats[256 + c] * invT;
    v = g_stats[384 + c] * invT - m * m;
    a = rsqrtf(v + BN_EPS) * gamG[c];
    g_scale[256 + c] = a;
    g_scale[384 + c] = betG[c] - m * a;
}

// ------------------------------------------------------------------
// pass D: update = silu(bn(core)) * sigmoid(bn(gate)); scatter-add by k_idx
// ------------------------------------------------------------------
__device__ __forceinline__ float sigf(float x) { return 1.0f / (1.0f + __expf(-x)); }

__global__ void pass_scatter(const int* __restrict__ kx, int T) {
    const int lane = threadIdx.x & 31;
    int warp = (blockIdx.x * blockDim.x + threadIdx.x) >> 5;
    const int nw = (gridDim.x * blockDim.x) >> 5;

    const float4 ac = reinterpret_cast<const float4*>(g_scale)[lane];
    const float4 bc = reinterpret_cast<const float4*>(g_scale + 128)[lane];
    const float4 ag = reinterpret_cast<const float4*>(g_scale + 256)[lane];
    const float4 bg = reinterpret_cast<const float4*>(g_scale + 384)[lane];

    for (int t = warp; t < T; t += nw) {
        int k = kx[t];
        const float4* A = reinterpret_cast<const float4*>(g_A + (size_t)t * 256);
        float4 c = A[lane];
        float4 g = A[lane + 32];

        float cnx = c.x * ac.x + bc.x, cny = c.y * ac.y + bc.y;
        float cnz = c.z * ac.z + bc.z, cnw = c.w * ac.w + bc.w;
        float gnx = g.x * ag.x + bg.x, gny = g.y * ag.y + bg.y;
        float gnz = g.z * ag.z + bg.z, gnw = g.w * ag.w + bg.w;

        float ux = cnx * sigf(cnx) * sigf(gnx);
        float uy = cny * sigf(cny) * sigf(gny);
        float uz = cnz * sigf(cnz) * sigf(gnz);
        float uw = cnw * sigf(cnw) * sigf(gnw);

        float* dst = g_seg + (size_t)k * 128 + lane * 4;
        atomicAdd(dst + 0, ux);
        atomicAdd(dst + 1, uy);
        atomicAdd(dst + 2, uz);
        atomicAdd(dst + 3, uw);
    }
}

// ------------------------------------------------------------------
extern "C" void kernel_launch(void* const* d_in, const int* in_sizes, int n_in,
                              void* d_out, int out_size) {
    const float* vertex = (const float*)d_in[0];
    const float* edge   = (const float*)d_in[1];
    const float* angle  = (const float*)d_in[2];
    // d_in[3] = edge_index (unused by the math)
    const int* kx = (const int*)d_in[4];
    const int* jx = (const int*)d_in[5];
    const int* ix = (const int*)d_in[6];
    const float* w_cs = (const float*)d_in[7];
    const float* w_cd = (const float*)d_in[8];
    const float* w_cb = (const float*)d_in[9];
    const float* w_ca = (const float*)d_in[10];
    const float* w_gs = (const float*)d_in[11];
    const float* w_gd = (const float*)d_in[12];
    const float* w_gb = (const float*)d_in[13];
    const float* w_ga = (const float*)d_in[14];
    const float* bcg = (const float*)d_in[15];
    const float* bcb = (const float*)d_in[16];
    const float* bgg = (const float*)d_in[17];
    const float* bgb = (const float*)d_in[18];
    const float* w_out = (const float*)d_in[19];

    const int N = in_sizes[0] / 128;
    const int E = in_sizes[1] / 128;
    const int T = in_sizes[2] / 64;

    float *pVsrc, *pVdst, *pEp, *pA, *pSeg;
    cudaGetSymbolAddress((void**)&pVsrc, g_Vsrc);
    cudaGetSymbolAddress((void**)&pVdst, g_Vdst);
    cudaGetSymbolAddress((void**)&pEp, g_Ep);
    cudaGetSymbolAddress((void**)&pA, g_A);
    cudaGetSymbolAddress((void**)&pSeg, g_seg);

    zero_kernel<<<2048, 256>>>(E);

    const int gN = (N + 127) / 128;
    const int gE = (E + 127) / 128;
    const int gT = (T + 127) / 128;

    // projections
    sgemm_xwT<<<gN, 256>>>(vertex, w_cs, nullptr, pVsrc, N, 128, 256, 0);
    sgemm_xwT<<<gN, 256>>>(vertex, w_gs, nullptr, pVsrc, N, 128, 256, 128);
    sgemm_xwT<<<gN, 256>>>(vertex, w_cd, nullptr, pVdst, N, 128, 256, 0);
    sgemm_xwT<<<gN, 256>>>(vertex, w_gd, nullptr, pVdst, N, 128, 256, 128);
    sgemm_xwT<<<gE, 256>>>(edge, w_cb, nullptr, pEp, E, 128, 256, 0);
    sgemm_xwT<<<gE, 256>>>(edge, w_gb, nullptr, pEp, E, 128, 256, 128);
    sgemm_xwT<<<gT, 256>>>(angle, w_ca, nullptr, pA, T, 64, 256, 0);
    sgemm_xwT<<<gT, 256>>>(angle, w_ga, nullptr, pA, T, 64, 256, 128);

    // gather-add + BN stats (in-place over g_A)
    pass_fuse<<<1184, 256>>>(kx, jx, ix, T);
    finalize_stats<<<1, 128>>>(bcg, bcb, bgg, bgb, 1.0f / (float)T);

    // activation + segment scatter
    pass_scatter<<<1184, 256>>>(kx, T);

    // new_bond = seg @ w_out.T + edge_feat
    sgemm_xwT<<<gE, 256>>>(pSeg, w_out, edge, (float*)d_out, E, 128, 128, 0);
}

// round 3
// speedup vs baseline: 1.4721x; 1.4721x over previous
#include <cuda_runtime.h>
#include <cstdint>

#define BN_EPS 1e-5f
#define MAXN 100000
#define MAXE 400000
#define MAXT 1000000

// ---- scratch (allocation-free, static device globals) ----
__device__ float g_Vsrc[(size_t)MAXN * 256];   // [N,256] = [core_src | gate_src]
__device__ float g_Vdst[(size_t)MAXN * 256];   // [N,256] = [core_dst | gate_dst]
__device__ float g_Ep  [(size_t)MAXE * 256];   // [E,256] = [core_bond | gate_bond]
__device__ float g_A   [(size_t)MAXT * 256];   // [T,256] angle proj -> fused core|gate
__device__ float g_seg [(size_t)MAXE * 128];   // segment sums
__device__ float g_stats[512];                 // sumC | ssqC | sumG | ssqG
__device__ float g_scale[512];                 // aC | bC | aG | bG
__device__ float g_Wvs[256 * 128];             // [w_core_src ; w_gate_src]
__device__ float g_Wvd[256 * 128];             // [w_core_dst ; w_gate_dst]
__device__ float g_Web[256 * 128];             // [w_core_bond ; w_gate_bond]
__device__ float g_Wan[256 * 64];              // [w_core_angle ; w_gate_angle]

// ------------------------------------------------------------------
__global__ void zero_kernel(int E) {
    size_t n4 = (size_t)E * 32;
    size_t i = (size_t)blockIdx.x * blockDim.x + threadIdx.x;
    size_t st = (size_t)gridDim.x * blockDim.x;
    float4 z = make_float4(0.f, 0.f, 0.f, 0.f);
    float4* p = reinterpret_cast<float4*>(g_seg);
    for (size_t k = i; k < n4; k += st) p[k] = z;
    if (i < 512) g_stats[i] = 0.f;
}

// pack [a;b] -> out [256,K]
__global__ void pack_weights(const float* __restrict__ a, const float* __restrict__ b,
                             float* __restrict__ out, int elems) {
    int i = blockIdx.x * blockDim.x + threadIdx.x;
    if (i < elems) { out[i] = a[i]; out[elems + i] = b[i]; }
}

__device__ __forceinline__ uint32_t to_tf32(float x) {
    uint32_t r;
    asm("cvt.rna.tf32.f32 %0, %1;" : "=r"(r) : "f"(x));
    return r;
}

// ------------------------------------------------------------------
// tf32 mma.sync GEMM: C[bx*128 + m, by*128 + n] = X @ W^T (+ Dadd)
// X: [M,K] row-major fp32. W: [Ntot,K] row-major fp32 (block uses rows
// by*128 .. by*128+127). 256 threads, block tile 128x128, warp tile 64x32.
// ------------------------------------------------------------------
template<int K>
__global__ __launch_bounds__(256, 2)
void mma_gemm(const float* __restrict__ X, const float* __restrict__ W,
              const float* __restrict__ Dadd, float* __restrict__ C,
              int M, int ldc) {
    constexpr int BK = 64;
    constexpr int KP = BK + 4;           // 68 floats -> conflict-free (stride mod 32 = 4)
    extern __shared__ float smem[];
    float* Xs = smem;                    // [128][KP]
    float* Ws = smem + 128 * KP;         // [128][KP]

    const int tid = threadIdx.x;
    const int lane = tid & 31;
    const int wid = tid >> 5;
    const int warpM = wid >> 2;          // 0..1
    const int warpN = wid & 3;           // 0..3
    const int g = lane >> 2;             // 0..7
    const int qc = lane & 3;             // 0..3
    const int row0 = blockIdx.x * 128;
    const int nBase = blockIdx.y * 128;

    float c[4][4][4];
#pragma unroll
    for (int mf = 0; mf < 4; ++mf)
#pragma unroll
        for (int nf = 0; nf < 4; ++nf)
#pragma unroll
            for (int q = 0; q < 4; ++q) c[mf][nf][q] = 0.f;

    for (int kt = 0; kt < K; kt += BK) {
        // load X tile [128 x BK] (fp32 -> tf32), zero outside M
        for (int i = tid; i < 128 * (BK / 4); i += 256) {
            int r = i >> 4;
            int k4 = (i & 15) << 2;
            int gr = row0 + r;
            float4 v = make_float4(0.f, 0.f, 0.f, 0.f);
            if (gr < M) v = *reinterpret_cast<const float4*>(X + (size_t)gr * K + kt + k4);
            uint32_t* dst = reinterpret_cast<uint32_t*>(Xs + r * KP + k4);
            dst[0] = to_tf32(v.x); dst[1] = to_tf32(v.y);
            dst[2] = to_tf32(v.z); dst[3] = to_tf32(v.w);
        }
        // load W tile [128 x BK]
        for (int i = tid; i < 128 * (BK / 4); i += 256) {
            int r = i >> 4;
            int k4 = (i & 15) << 2;
            float4 v = *reinterpret_cast<const float4*>(W + (size_t)(nBase + r) * K + kt + k4);
            uint32_t* dst = reinterpret_cast<uint32_t*>(Ws + r * KP + k4);
            dst[0] = to_tf32(v.x); dst[1] = to_tf32(v.y);
            dst[2] = to_tf32(v.z); dst[3] = to_tf32(v.w);
        }
        __syncthreads();

        const uint32_t* Xu = reinterpret_cast<const uint32_t*>(Xs);
        const uint32_t* Wu = reinterpret_cast<const uint32_t*>(Ws);
#pragma unroll
        for (int k0 = 0; k0 < BK; k0 += 8) {
            uint32_t a[4][4], b[4][2];
#pragma unroll
            for (int mf = 0; mf < 4; ++mf) {
                int r = warpM * 64 + mf * 16 + g;
                a[mf][0] = Xu[r * KP + k0 + qc];
                a[mf][1] = Xu[(r + 8) * KP + k0 + qc];
                a[mf][2] = Xu[r * KP + k0 + qc + 4];
                a[mf][3] = Xu[(r + 8) * KP + k0 + qc + 4];
            }
#pragma unroll
            for (int nf = 0; nf < 4; ++nf) {
                int n = warpN * 32 + nf * 8 + g;
                b[nf][0] = Wu[n * KP + k0 + qc];
                b[nf][1] = Wu[n * KP + k0 + qc + 4];
            }
#pragma unroll
            for (int mf = 0; mf < 4; ++mf)
#pragma unroll
                for (int nf = 0; nf < 4; ++nf) {
                    asm volatile(
                        "mma.sync.aligned.m16n8k8.row.col.f32.tf32.tf32.f32 "
                        "{%0,%1,%2,%3}, {%4,%5,%6,%7}, {%8,%9}, {%0,%1,%2,%3};"
                        : "+f"(c[mf][nf][0]), "+f"(c[mf][nf][1]),
                          "+f"(c[mf][nf][2]), "+f"(c[mf][nf][3])
                        : "r"(a[mf][0]), "r"(a[mf][1]), "r"(a[mf][2]), "r"(a[mf][3]),
                          "r"(b[nf][0]), "r"(b[nf][1]));
                }
        }
        __syncthreads();
    }

    // epilogue
#pragma unroll
    for (int mf = 0; mf < 4; ++mf) {
        int r0 = row0 + warpM * 64 + mf * 16 + g;
        int r1 = r0 + 8;
#pragma unroll
        for (int nf = 0; nf < 4; ++nf) {
            int col = nBase + warpN * 32 + nf * 8 + qc * 2;
            if (r0 < M) {
                float2 o = make_float2(c[mf][nf][0], c[mf][nf][1]);
                if (Dadd) {
                    float2 d = *reinterpret_cast<const float2*>(Dadd + (size_t)r0 * ldc + col);
                    o.x += d.x; o.y += d.y;
                }
                *reinterpret_cast<float2*>(C + (size_t)r0 * ldc + col) = o;
            }
            if (r1 < M) {
                float2 o = make_float2(c[mf][nf][2], c[mf][nf][3]);
                if (Dadd) {
                    float2 d = *reinterpret_cast<const float2*>(Dadd + (size_t)r1 * ldc + col);
                    o.x += d.x; o.y += d.y;
                }
                *reinterpret_cast<float2*>(C + (size_t)r1 * ldc + col) = o;
            }
        }
    }
}

// ------------------------------------------------------------------
// pass B: core/gate = A + Vsrc[j] + Ep[k] + Vdst[i] (in place), + BN stats
// ------------------------------------------------------------------
__device__ __forceinline__ float4 f4add(float4 a, float4 b) {
    return make_float4(a.x + b.x, a.y + b.y, a.z + b.z, a.w + b.w);
}

__global__ void pass_fuse(const int* __restrict__ kx, const int* __restrict__ jx,
                          const int* __restrict__ ix, int T) {
    const int lane = threadIdx.x & 31;
    int warp = (blockIdx.x * blockDim.x + threadIdx.x) >> 5;
    const int nw = (gridDim.x * blockDim.x) >> 5;

    float4 sc = make_float4(0, 0, 0, 0), qc = make_float4(0, 0, 0, 0);
    float4 sg = make_float4(0, 0, 0, 0), qg = make_float4(0, 0, 0, 0);

    for (int t = warp; t < T; t += nw) {
        int j = jx[t], k = kx[t], i = ix[t];
        float4* A        = reinterpret_cast<float4*>(g_A + (size_t)t * 256);
        const float4* Vs = reinterpret_cast<const float4*>(g_Vsrc + (size_t)j * 256);
        const float4* Ep = reinterpret_cast<const float4*>(g_Ep + (size_t)k * 256);
        const float4* Vd = reinterpret_cast<const float4*>(g_Vdst + (size_t)i * 256);

        float4 c = f4add(f4add(A[lane], Vs[lane]), f4add(Ep[lane], Vd[lane]));
        float4 g = f4add(f4add(A[lane + 32], Vs[lane + 32]),
                         f4add(Ep[lane + 32], Vd[lane + 32]));
        A[lane] = c;
        A[lane + 32] = g;

        sc = f4add(sc, c);
        qc = f4add(qc, make_float4(c.x * c.x, c.y * c.y, c.z * c.z, c.w * c.w));
        sg = f4add(sg, g);
        qg = f4add(qg, make_float4(g.x * g.x, g.y * g.y, g.z * g.z, g.w * g.w));
    }

    int c0 = lane * 4;
    atomicAdd(&g_stats[c0 + 0], sc.x); atomicAdd(&g_stats[c0 + 1], sc.y);
    atomicAdd(&g_stats[c0 + 2], sc.z); atomicAdd(&g_stats[c0 + 3], sc.w);
    atomicAdd(&g_stats[128 + c0 + 0], qc.x); atomicAdd(&g_stats[128 + c0 + 1], qc.y);
    atomicAdd(&g_stats[128 + c0 + 2], qc.z); atomicAdd(&g_stats[128 + c0 + 3], qc.w);
    atomicAdd(&g_stats[256 + c0 + 0], sg.x); atomicAdd(&g_stats[256 + c0 + 1], sg.y);
    atomicAdd(&g_stats[256 + c0 + 2], sg.z); atomicAdd(&g_stats[256 + c0 + 3], sg.w);
    atomicAdd(&g_stats[384 + c0 + 0], qg.x); atomicAdd(&g_stats[384 + c0 + 1], qg.y);
    atomicAdd(&g_stats[384 + c0 + 2], qg.z); atomicAdd(&g_stats[384 + c0 + 3], qg.w);
}

// ------------------------------------------------------------------
__global__ void finalize_stats(const float* __restrict__ gamC, const float* __restrict__ betC,
                               const float* __restrict__ gamG, const float* __restrict__ betG,
                               float invT) {
    int c = threadIdx.x;  // 128 threads
    float m = g_stats[c] * invT;
    float v = g_stats[128 + c] * invT - m * m;
    float a = rsqrtf(v + BN_EPS) * gamC[c];
    g_scale[c] = a;
    g_scale[128 + c] = betC[c] - m * a;

    m = g_stats[256 + c] * invT;
    v = g_stats[384 + c] * invT - m * m;
    a = rsqrtf(v + BN_EPS) * gamG[c];
    g_scale[256 + c] = a;
    g_scale[384 + c] = betG[c] - m * a;
}

// ------------------------------------------------------------------
__device__ __forceinline__ float sigf(float x) { return 1.0f / (1.0f + __expf(-x)); }

__global__ void pass_scatter(const int* __restrict__ kx, int T) {
    const int lane = threadIdx.x & 31;
    int warp = (blockIdx.x * blockDim.x + threadIdx.x) >> 5;
    const int nw = (gridDim.x * blockDim.x) >> 5;

    const float4 ac = reinterpret_cast<const float4*>(g_scale)[lane];
    const float4 bc = reinterpret_cast<const float4*>(g_scale + 128)[lane];
    const float4 ag = reinterpret_cast<const float4*>(g_scale + 256)[lane];
    const float4 bg = reinterpret_cast<const float4*>(g_scale + 384)[lane];

    for (int t = warp; t < T; t += nw) {
        int k = kx[t];
        const float4* A = reinterpret_cast<const float4*>(g_A + (size_t)t * 256);
        float4 c = A[lane];
        float4 g = A[lane + 32];

        float cnx = c.x * ac.x + bc.x, cny = c.y * ac.y + bc.y;
        float cnz = c.z * ac.z + bc.z, cnw = c.w * ac.w + bc.w;
        float gnx = g.x * ag.x + bg.x, gny = g.y * ag.y + bg.y;
        float gnz = g.z * ag.z + bg.z, gnw = g.w * ag.w + bg.w;

        float ux = cnx * sigf(cnx) * sigf(gnx);
        float uy = cny * sigf(cny) * sigf(gny);
        float uz = cnz * sigf(cnz) * sigf(gnz);
        float uw = cnw * sigf(cnw) * sigf(gnw);

        float* dst = g_seg + (size_t)k * 128 + lane * 4;
        atomicAdd(dst + 0, ux);
        atomicAdd(dst + 1, uy);
        atomicAdd(dst + 2, uz);
        atomicAdd(dst + 3, uw);
    }
}

// ------------------------------------------------------------------
extern "C" void kernel_launch(void* const* d_in, const int* in_sizes, int n_in,
                              void* d_out, int out_size) {
    const float* vertex = (const float*)d_in[0];
    const float* edge   = (const float*)d_in[1];
    const float* angle  = (const float*)d_in[2];
    const int* kx = (const int*)d_in[4];
    const int* jx = (const int*)d_in[5];
    const int* ix = (const int*)d_in[6];
    const float* w_cs = (const float*)d_in[7];
    const float* w_cd = (const float*)d_in[8];
    const float* w_cb = (const float*)d_in[9];
    const float* w_ca = (const float*)d_in[10];
    const float* w_gs = (const float*)d_in[11];
    const float* w_gd = (const float*)d_in[12];
    const float* w_gb = (const float*)d_in[13];
    const float* w_ga = (const float*)d_in[14];
    const float* bcg = (const float*)d_in[15];
    const float* bcb = (const float*)d_in[16];
    const float* bgg = (const float*)d_in[17];
    const float* bgb = (const float*)d_in[18];
    const float* w_out = (const float*)d_in[19];

    const int N = in_sizes[0] / 128;
    const int E = in_sizes[1] / 128;
    const int T = in_sizes[2] / 64;

    float *pVsrc, *pVdst, *pEp, *pA, *pSeg, *pWvs, *pWvd, *pWeb, *pWan;
    cudaGetSymbolAddress((void**)&pVsrc, g_Vsrc);
    cudaGetSymbolAddress((void**)&pVdst, g_Vdst);
    cudaGetSymbolAddress((void**)&pEp, g_Ep);
    cudaGetSymbolAddress((void**)&pA, g_A);
    cudaGetSymbolAddress((void**)&pSeg, g_seg);
    cudaGetSymbolAddress((void**)&pWvs, g_Wvs);
    cudaGetSymbolAddress((void**)&pWvd, g_Wvd);
    cudaGetSymbolAddress((void**)&pWeb, g_Web);
    cudaGetSymbolAddress((void**)&pWan, g_Wan);

    const size_t smem_bytes = 2 * 128 * 68 * sizeof(float);  // 69632
    cudaFuncSetAttribute(mma_gemm<128>, cudaFuncAttributeMaxDynamicSharedMemorySize,
                         (int)smem_bytes);
    cudaFuncSetAttribute(mma_gemm<64>, cudaFuncAttributeMaxDynamicSharedMemorySize,
                         (int)smem_bytes);

    zero_kernel<<<2048, 256>>>(E);
    pack_weights<<<64, 256>>>(w_cs, w_gs, pWvs, 16384);
    pack_weights<<<64, 256>>>(w_cd, w_gd, pWvd, 16384);
    pack_weights<<<64, 256>>>(w_cb, w_gb, pWeb, 16384);
    pack_weights<<<32, 256>>>(w_ca, w_ga, pWan, 8192);

    const int gN = (N + 127) / 128;
    const int gE = (E + 127) / 128;
    const int gT = (T + 127) / 128;

    // projections: core|gate packed -> N dimension 256 via gridDim.y = 2
    mma_gemm<128><<<dim3(gN, 2), 256, smem_bytes>>>(vertex, pWvs, nullptr, pVsrc, N, 256);
    mma_gemm<128><<<dim3(gN, 2), 256, smem_bytes>>>(vertex, pWvd, nullptr, pVdst, N, 256);
    mma_gemm<128><<<dim3(gE, 2), 256, smem_bytes>>>(edge,   pWeb, nullptr, pEp,   E, 256);
    mma_gemm<64> <<<dim3(gT, 2), 256, smem_bytes>>>(angle,  pWan, nullptr, pA,    T, 256);

    // gather-add + BN stats (in-place over g_A)
    pass_fuse<<<1184, 256>>>(kx, jx, ix, T);
    finalize_stats<<<1, 128>>>(bcg, bcb, bgg, bgb, 1.0f / (float)T);

    // activation + segment scatter
    pass_scatter<<<1184, 256>>>(kx, T);

    // new_bond = seg @ w_out.T + edge_feat
    mma_gemm<128><<<dim3(gE, 1), 256, smem_bytes>>>(pSeg, w_out, edge, (float*)d_out, E, 128);
}